// round 8
// baseline (speedup 1.0000x reference)
#include <cuda_runtime.h>
#include <cuda_bf16.h>
#include <math_constants.h>

// Problem constants
#define NSEQ 2048
#define DMODEL 1024
#define NHEAD 16
#define HDIM 64
#define QKV_W (3 * DMODEL)   // 3072

// ---------------------------------------------------------------------------
// Scratch (__device__ globals; no allocations allowed)
// ---------------------------------------------------------------------------
__device__ float g_qkv [NSEQ * QKV_W];     // q|k|v, fp32
__device__ float g_gate[NSEQ * DMODEL];    // sigmoid(x Wg^T + bg), fp32
__device__ float g_attn[NSEQ * DMODEL];    // (attn*gate), tf32-rounded
__device__ float g_xr   [NSEQ * DMODEL];   // tf32-rounded x
__device__ float g_wqkvr[QKV_W * DMODEL];  // tf32-rounded Wqkv
__device__ float g_wgatr[DMODEL * DMODEL]; // tf32-rounded Wgate
__device__ float g_woutr[DMODEL * DMODEL]; // tf32-rounded Wout

__device__ __forceinline__ float rna_tf32(float x) {
    float y;
    asm("cvt.rna.tf32.f32 %0, %1;" : "=f"(y) : "f"(x));
    return y;
}

// ---------------------------------------------------------------------------
// Single merged tf32-rounding pass over x, Wqkv, Wgate, Wout
// ---------------------------------------------------------------------------
#define RN0 (NSEQ * DMODEL / 4)      // x      : 524288 float4
#define RN1 (QKV_W * DMODEL / 4)     // Wqkv   : 786432
#define RN2 (DMODEL * DMODEL / 4)    // Wgate  : 262144
#define RN3 (DMODEL * DMODEL / 4)    // Wout   : 262144

__global__ void round_all(const float4* __restrict__ x,  float4* __restrict__ xr,
                          const float4* __restrict__ wq, float4* __restrict__ wqr,
                          const float4* __restrict__ wg, float4* __restrict__ wgr,
                          const float4* __restrict__ wo, float4* __restrict__ wor)
{
    const int total = RN0 + RN1 + RN2 + RN3;
    int i = blockIdx.x * blockDim.x + threadIdx.x;
    const int stride = gridDim.x * blockDim.x;
    for (; i < total; i += stride) {
        const float4* src; float4* dst; int j = i;
        if (j < RN0)              { src = x;  dst = xr; }
        else if ((j -= RN0) < RN1){ src = wq; dst = wqr; }
        else if ((j -= RN1) < RN2){ src = wg; dst = wgr; }
        else { j -= RN2;            src = wo; dst = wor; }
        float4 v = src[j];
        v.x = rna_tf32(v.x); v.y = rna_tf32(v.y);
        v.z = rna_tf32(v.z); v.w = rna_tf32(v.w);
        dst[j] = v;
    }
}

// ---------------------------------------------------------------------------
// tf32 tensor-core GEMM: C[M,Nn] = A[M,K] @ W[Nn,K]^T + bias  (act=1: sigmoid)
// 128x128 CTA tile, BK=8, 4-stage cp.async pipeline, ONE sync per k-iter,
// 8 warps (4x2), 32x64 warp tile, mma.sync.m16n8k8.
// Smem: 4 stages x (128+128) rows x 12 words = 49152 B (exactly 48 KB).
// LDSD=12: fragment LDS addr = 12*qr + qk (+4) -> all 32 banks distinct.
// ---------------------------------------------------------------------------
#define BM 128
#define BN 128
#define BKT 8
#define LDSD 12
#define NSTG 4
#define STGW ((BM + BN) * LDSD)    // 3072 words per stage

__device__ __forceinline__ void mma16n8k8(float* c, const unsigned* a, const unsigned* b)
{
    asm volatile(
        "mma.sync.aligned.m16n8k8.row.col.f32.tf32.tf32.f32 "
        "{%0,%1,%2,%3}, {%4,%5,%6,%7}, {%8,%9}, {%0,%1,%2,%3};\n"
        : "+f"(c[0]), "+f"(c[1]), "+f"(c[2]), "+f"(c[3])
        : "r"(a[0]), "r"(a[1]), "r"(a[2]), "r"(a[3]), "r"(b[0]), "r"(b[1]));
}

#define CP16(sm, gp) \
    asm volatile("cp.async.cg.shared.global [%0], [%1], 16;\n" :: "r"(sm), "l"(gp) : "memory")
#define CP_COMMIT() asm volatile("cp.async.commit_group;\n" ::: "memory")
#define CP_WAIT2()  asm volatile("cp.async.wait_group 2;\n" ::: "memory")

__global__ __launch_bounds__(256, 2)
void mma_gemm(const float* __restrict__ A, const float* __restrict__ W,
              const float* __restrict__ bias, float* __restrict__ C,
              int M, int Nn, int K, int act)
{
    __shared__ __align__(16) unsigned Sh[NSTG][STGW];

    const int tid  = threadIdx.x;
    const int lane = tid & 31;
    const int wid  = tid >> 5;
    const int wm   = wid & 3;          // 4 warps along M (32 rows each)
    const int wn   = wid >> 2;         // 2 warps along N (64 cols each)
    const int row0 = blockIdx.y * BM;
    const int col0 = blockIdx.x * BN;

    // copy mapping: 256 threads cover 128 rows x 2 float4 per operand
    const int cpr = tid >> 1;          // 0..127
    const int cpc = (tid & 1) * 4;     // 0 or 4

    const float* Ag = A + (size_t)(row0 + cpr) * K + cpc;
    const float* Wg = W + (size_t)(col0 + cpr) * K + cpc;

    const unsigned shbase = (unsigned)__cvta_generic_to_shared(&Sh[0][0]);
    const unsigned aoff = (cpr * LDSD + cpc) * 4;
    const unsigned boff = (BM * LDSD + cpr * LDSD + cpc) * 4;

    float acc[2][8][4];
#pragma unroll
    for (int mt = 0; mt < 2; mt++)
#pragma unroll
        for (int nt = 0; nt < 8; nt++)
#pragma unroll
            for (int i = 0; i < 4; i++) acc[mt][nt][i] = 0.0f;

    const int T = K / BKT;

    // prologue: stages 0..2
#pragma unroll
    for (int s = 0; s < NSTG - 1; s++) {
        const unsigned sb = shbase + s * STGW * 4;
        CP16(sb + aoff, Ag + s * BKT);
        CP16(sb + boff, Wg + s * BKT);
        CP_COMMIT();
    }

    const int qk = lane & 3;
    const int qr = lane >> 2;

    for (int t = 0; t < T; t++) {
        CP_WAIT2();            // stage t complete (<=2 younger groups pending)
        __syncthreads();       // all warps done with stage (t-1)%4 reads

        if (t + NSTG - 1 < T) {
            const int s = (t + NSTG - 1) & 3;
            const unsigned sb = shbase + s * STGW * 4;
            CP16(sb + aoff, Ag + (t + NSTG - 1) * BKT);
            CP16(sb + boff, Wg + (t + NSTG - 1) * BKT);
        }
        CP_COMMIT();

        const unsigned* as = &Sh[t & 3][0];
        const unsigned* bs = &Sh[t & 3][BM * LDSD];

        unsigned bfr[8][2];
#pragma unroll
        for (int nt = 0; nt < 8; nt++) {
            const int n = wn * 64 + nt * 8 + qr;
            bfr[nt][0] = bs[n * LDSD + qk];
            bfr[nt][1] = bs[n * LDSD + qk + 4];
        }
        unsigned afr[2][4];
#pragma unroll
        for (int mt = 0; mt < 2; mt++) {
            const int m = wm * 32 + mt * 16 + qr;
            afr[mt][0] = as[m * LDSD + qk];
            afr[mt][1] = as[(m + 8) * LDSD + qk];
            afr[mt][2] = as[m * LDSD + qk + 4];
            afr[mt][3] = as[(m + 8) * LDSD + qk + 4];
        }
#pragma unroll
        for (int mt = 0; mt < 2; mt++)
#pragma unroll
            for (int nt = 0; nt < 8; nt++)
                mma16n8k8(acc[mt][nt], afr[mt], bfr[nt]);
    }

    // epilogue: bias (+ optional sigmoid), float2 stores
#pragma unroll
    for (int mt = 0; mt < 2; mt++) {
        const int r0 = row0 + wm * 32 + mt * 16 + qr;
#pragma unroll
        for (int nt = 0; nt < 8; nt++) {
            const int c = col0 + wn * 64 + nt * 8 + qk * 2;
            const float2 bv = *(const float2*)&bias[c];
            float v0 = acc[mt][nt][0] + bv.x;
            float v1 = acc[mt][nt][1] + bv.y;
            float v2 = acc[mt][nt][2] + bv.x;
            float v3 = acc[mt][nt][3] + bv.y;
            if (act) {
                v0 = 1.0f / (1.0f + __expf(-v0));
                v1 = 1.0f / (1.0f + __expf(-v1));
                v2 = 1.0f / (1.0f + __expf(-v2));
                v3 = 1.0f / (1.0f + __expf(-v3));
            }
            *(float2*)&C[(size_t)r0 * Nn + c]       = make_float2(v0, v1);
            *(float2*)&C[(size_t)(r0 + 8) * Nn + c] = make_float2(v2, v3);
        }
    }
}

// ---------------------------------------------------------------------------
// Offset attention + gate fuse. One warp per (n, h) pair.
// Block covers 16 consecutive n of the SAME head -> K/V rows overlap 73/74
// between neighboring warps, so the dense window stays L1-resident.
// ---------------------------------------------------------------------------
#define WPB 16

__global__ __launch_bounds__(WPB * 32)
void attn_kernel(const float* __restrict__ qkv, const float* __restrict__ gate,
                 const float* __restrict__ pos_bias, const int* __restrict__ offsets,
                 float* __restrict__ attn_out, int NO)
{
    __shared__ __align__(16) float q_sh[WPB][HDIM];
    __shared__ float sc_sh[WPB][96];
    __shared__ int offs_sh[96];

    const int tid = threadIdx.x;
    const int w = tid >> 5;
    const int l = tid & 31;

    for (int i = tid; i < NO; i += blockDim.x) offs_sh[i] = offsets[i];
    __syncthreads();

    const int pair = blockIdx.x * WPB + w;        // [0, NHEAD*NSEQ)
    const int h = pair >> 11;                     // same head per block
    const int n = pair & (NSEQ - 1);              // 16 consecutive n per block

    const float* qrow  = qkv + (size_t)n * QKV_W + h * HDIM;
    const float* Kbase = qkv + DMODEL     + h * HDIM;
    const float* Vbase = qkv + 2 * DMODEL + h * HDIM;

    float2 q2 = *(const float2*)(qrow + 2 * l);
    q_sh[w][2 * l]     = q2.x;
    q_sh[w][2 * l + 1] = q2.y;
    __syncwarp();

    float sloc[3];
    float m = -CUDART_INF_F;
#pragma unroll
    for (int j = 0; j < 3; j++) {
        const int o = l + 32 * j;
        float s = -CUDART_INF_F;
        if (o < NO) {
            const int idx = n - offs_sh[o];
            if (idx >= 0) {
                const float* krow = Kbase + (size_t)idx * QKV_W;
                float a = 0.0f;
#pragma unroll
                for (int d = 0; d < HDIM; d += 4) {
                    float4 kv = *(const float4*)(krow + d);
                    float4 qv = *(const float4*)(&q_sh[w][d]);
                    a += kv.x * qv.x + kv.y * qv.y + kv.z * qv.z + kv.w * qv.w;
                }
                s = a * 0.125f + pos_bias[o * NHEAD + h];
            }
        }
        sloc[j] = s;
        m = fmaxf(m, s);
    }
#pragma unroll
    for (int off = 16; off > 0; off >>= 1)
        m = fmaxf(m, __shfl_xor_sync(0xFFFFFFFFu, m, off));

    float ssum = 0.0f;
    float eloc[3];
#pragma unroll
    for (int j = 0; j < 3; j++) {
        float e = (sloc[j] == -CUDART_INF_F) ? 0.0f : __expf(sloc[j] - m);
        eloc[j] = e;
        ssum += e;
    }
#pragma unroll
    for (int off = 16; off > 0; off >>= 1)
        ssum += __shfl_xor_sync(0xFFFFFFFFu, ssum, off);

    const float inv = 1.0f / ssum;
#pragma unroll
    for (int j = 0; j < 3; j++) {
        const int o = l + 32 * j;
        if (o < NO) sc_sh[w][o] = eloc[j] * inv;
    }
    __syncwarp();

    float ax = 0.0f, ay = 0.0f;
    for (int o = 0; o < NO; o++) {
        const float a = sc_sh[w][o];
        int idx = n - offs_sh[o];
        if (idx < 0) idx = 0;                       // alpha==0 there anyway
        const float2 v2 = *(const float2*)(Vbase + (size_t)idx * QKV_W + 2 * l);
        ax += a * v2.x;
        ay += a * v2.y;
    }

    const int col = h * HDIM + 2 * l;
    const float2 g = *(const float2*)(gate + (size_t)n * DMODEL + col);
    float2 r;
    r.x = rna_tf32(ax * g.x);   // pre-round: out-proj reads this as tf32 A
    r.y = rna_tf32(ay * g.y);
    *(float2*)(attn_out + (size_t)n * DMODEL + col) = r;
}

// ---------------------------------------------------------------------------
// Launch
// ---------------------------------------------------------------------------
extern "C" void kernel_launch(void* const* d_in, const int* in_sizes, int n_in,
                              void* d_out, int out_size)
{
    const float* x        = (const float*)d_in[0];
    const float* Wqkv     = (const float*)d_in[1];
    const float* bqkv     = (const float*)d_in[2];
    const float* Wgate    = (const float*)d_in[3];
    const float* bgate    = (const float*)d_in[4];
    const float* Wout     = (const float*)d_in[5];
    const float* bout     = (const float*)d_in[6];
    const float* pos_bias = (const float*)d_in[7];
    const int*   offsets  = (const int*)d_in[8];
    const int NO = in_sizes[8];

    float *qkv_p, *gate_p, *attn_p, *xr_p, *wqkvr_p, *wgatr_p, *woutr_p;
    cudaGetSymbolAddress((void**)&qkv_p,   g_qkv);
    cudaGetSymbolAddress((void**)&gate_p,  g_gate);
    cudaGetSymbolAddress((void**)&attn_p,  g_attn);
    cudaGetSymbolAddress((void**)&xr_p,    g_xr);
    cudaGetSymbolAddress((void**)&wqkvr_p, g_wqkvr);
    cudaGetSymbolAddress((void**)&wgatr_p, g_wgatr);
    cudaGetSymbolAddress((void**)&woutr_p, g_woutr);

    // 0) tf32-round all GEMM operands in one pass
    round_all<<<1184, 256>>>((const float4*)x,     (float4*)xr_p,
                             (const float4*)Wqkv,  (float4*)wqkvr_p,
                             (const float4*)Wgate, (float4*)wgatr_p,
                             (const float4*)Wout,  (float4*)woutr_p);

    // 1) qkv = x @ Wqkv^T + bqkv
    mma_gemm<<<dim3(QKV_W / BN, NSEQ / BM), 256>>>(
        xr_p, wqkvr_p, bqkv, qkv_p, NSEQ, QKV_W, DMODEL, 0);

    // 2) gate = sigmoid(x @ Wgate^T + bgate)
    mma_gemm<<<dim3(DMODEL / BN, NSEQ / BM), 256>>>(
        xr_p, wgatr_p, bgate, gate_p, NSEQ, DMODEL, DMODEL, 1);

    // 3) attention + gate multiply (tf32-rounded output)
    attn_kernel<<<(NSEQ * NHEAD) / WPB, WPB * 32>>>(
        qkv_p, gate_p, pos_bias, offsets, attn_p, NO);

    // 4) out = (attn*gate) @ Wout^T + bout
    mma_gemm<<<dim3(DMODEL / BN, NSEQ / BM), 256>>>(
        attn_p, woutr_p, bout, (float*)d_out, NSEQ, DMODEL, DMODEL, 0);
}

// round 9
// speedup vs baseline: 1.3930x; 1.3930x over previous
#include <cuda_runtime.h>
#include <cuda_bf16.h>
#include <math_constants.h>

// Problem constants
#define NSEQ 2048
#define DMODEL 1024
#define NHEAD 16
#define HDIM 64
#define QKV_W (3 * DMODEL)   // 3072

// ---------------------------------------------------------------------------
// Scratch (__device__ globals; no allocations allowed)
// ---------------------------------------------------------------------------
__device__ float g_qkv [NSEQ * QKV_W];     // q|k|v, fp32
__device__ float g_gate[NSEQ * DMODEL];    // sigmoid(x Wg^T + bg), fp32
__device__ float g_attn[NSEQ * DMODEL];    // (attn*gate), tf32-rounded
__device__ float g_xr   [NSEQ * DMODEL];   // tf32-rounded x
__device__ float g_wqkvr[QKV_W * DMODEL];  // tf32-rounded Wqkv
__device__ float g_wgatr[DMODEL * DMODEL]; // tf32-rounded Wgate
__device__ float g_woutr[DMODEL * DMODEL]; // tf32-rounded Wout

__device__ __forceinline__ float rna_tf32(float x) {
    float y;
    asm("cvt.rna.tf32.f32 %0, %1;" : "=f"(y) : "f"(x));
    return y;
}

__device__ __forceinline__ void mma16n8k8(float* c, const unsigned* a, const unsigned* b)
{
    asm volatile(
        "mma.sync.aligned.m16n8k8.row.col.f32.tf32.tf32.f32 "
        "{%0,%1,%2,%3}, {%4,%5,%6,%7}, {%8,%9}, {%0,%1,%2,%3};\n"
        : "+f"(c[0]), "+f"(c[1]), "+f"(c[2]), "+f"(c[3])
        : "r"(a[0]), "r"(a[1]), "r"(a[2]), "r"(a[3]), "r"(b[0]), "r"(b[1]));
}

// ---------------------------------------------------------------------------
// Single merged tf32-rounding pass over x, Wqkv, Wgate, Wout
// ---------------------------------------------------------------------------
#define RN0 (NSEQ * DMODEL / 4)
#define RN1 (QKV_W * DMODEL / 4)
#define RN2 (DMODEL * DMODEL / 4)
#define RN3 (DMODEL * DMODEL / 4)

__global__ void round_all(const float4* __restrict__ x,  float4* __restrict__ xr,
                          const float4* __restrict__ wq, float4* __restrict__ wqr,
                          const float4* __restrict__ wg, float4* __restrict__ wgr,
                          const float4* __restrict__ wo, float4* __restrict__ wor)
{
    const int total = RN0 + RN1 + RN2 + RN3;
    int i = blockIdx.x * blockDim.x + threadIdx.x;
    const int stride = gridDim.x * blockDim.x;
    for (; i < total; i += stride) {
        const float4* src; float4* dst; int j = i;
        if (j < RN0)              { src = x;  dst = xr; }
        else if ((j -= RN0) < RN1){ src = wq; dst = wqr; }
        else if ((j -= RN1) < RN2){ src = wg; dst = wgr; }
        else { j -= RN2;            src = wo; dst = wor; }
        float4 v = src[j];
        v.x = rna_tf32(v.x); v.y = rna_tf32(v.y);
        v.z = rna_tf32(v.z); v.w = rna_tf32(v.w);
        dst[j] = v;
    }
}

// ---------------------------------------------------------------------------
// tf32 tensor-core GEMM (round-7 proven version): C = A @ W^T + bias
// 128x128 tile, BK=16, double-buffered cp.async, 8 warps, 32x64 warp tile.
// ---------------------------------------------------------------------------
#define BM 128
#define BN 128
#define BKT 16
#define LDSD 20

#define CP16(sm, gp) \
    asm volatile("cp.async.cg.shared.global [%0], [%1], 16;\n" :: "r"(sm), "l"(gp) : "memory")

__global__ __launch_bounds__(256, 2)
void mma_gemm(const float* __restrict__ A, const float* __restrict__ W,
              const float* __restrict__ bias, float* __restrict__ C,
              int M, int Nn, int K, int act)
{
    __shared__ __align__(16) unsigned As[2][BM * LDSD];
    __shared__ __align__(16) unsigned Bs[2][BN * LDSD];

    const int tid  = threadIdx.x;
    const int lane = tid & 31;
    const int wid  = tid >> 5;
    const int wm   = wid & 3;
    const int wn   = wid >> 2;
    const int row0 = blockIdx.y * BM;
    const int col0 = blockIdx.x * BN;

    const int cpr = tid >> 2;
    const int cpc = (tid & 3) * 4;

    const float* Ag = A + (size_t)(row0 + cpr) * K + cpc;
    const float* Wg = W + (size_t)(col0 + cpr) * K + cpc;

    unsigned sA[2], sB[2];
    sA[0] = (unsigned)__cvta_generic_to_shared(&As[0][cpr * LDSD + cpc]);
    sA[1] = (unsigned)__cvta_generic_to_shared(&As[1][cpr * LDSD + cpc]);
    sB[0] = (unsigned)__cvta_generic_to_shared(&Bs[0][cpr * LDSD + cpc]);
    sB[1] = (unsigned)__cvta_generic_to_shared(&Bs[1][cpr * LDSD + cpc]);
    const unsigned off64 = 64 * LDSD * 4;
    const size_t   goff64 = (size_t)64 * K;

    float acc[2][8][4];
#pragma unroll
    for (int mt = 0; mt < 2; mt++)
#pragma unroll
        for (int nt = 0; nt < 8; nt++)
#pragma unroll
            for (int i = 0; i < 4; i++) acc[mt][nt][i] = 0.0f;

    const int T = K / BKT;

    CP16(sA[0],         Ag);
    CP16(sA[0] + off64, Ag + goff64);
    CP16(sB[0],         Wg);
    CP16(sB[0] + off64, Wg + goff64);
    asm volatile("cp.async.commit_group;\n" ::: "memory");

    const int qk = lane & 3;
    const int qr = lane >> 2;

    for (int t = 0; t < T; t++) {
        const int buf = t & 1;
        if (t + 1 < T) {
            const int nb = buf ^ 1;
            const int k1 = (t + 1) * BKT;
            CP16(sA[nb],         Ag + k1);
            CP16(sA[nb] + off64, Ag + k1 + goff64);
            CP16(sB[nb],         Wg + k1);
            CP16(sB[nb] + off64, Wg + k1 + goff64);
        }
        asm volatile("cp.async.commit_group;\n" ::: "memory");
        asm volatile("cp.async.wait_group 1;\n" ::: "memory");
        __syncthreads();

        const unsigned* as = As[buf];
        const unsigned* bs = Bs[buf];
#pragma unroll
        for (int ks = 0; ks < 2; ks++) {
            unsigned bfr[8][2];
#pragma unroll
            for (int nt = 0; nt < 8; nt++) {
                const int n = wn * 64 + nt * 8 + qr;
                bfr[nt][0] = bs[n * LDSD + ks * 8 + qk];
                bfr[nt][1] = bs[n * LDSD + ks * 8 + qk + 4];
            }
            unsigned afr[2][4];
#pragma unroll
            for (int mt = 0; mt < 2; mt++) {
                const int m = wm * 32 + mt * 16 + qr;
                afr[mt][0] = as[m * LDSD + ks * 8 + qk];
                afr[mt][1] = as[(m + 8) * LDSD + ks * 8 + qk];
                afr[mt][2] = as[m * LDSD + ks * 8 + qk + 4];
                afr[mt][3] = as[(m + 8) * LDSD + ks * 8 + qk + 4];
            }
#pragma unroll
            for (int mt = 0; mt < 2; mt++)
#pragma unroll
                for (int nt = 0; nt < 8; nt++)
                    mma16n8k8(acc[mt][nt], afr[mt], bfr[nt]);
        }
        __syncthreads();
    }

#pragma unroll
    for (int mt = 0; mt < 2; mt++) {
        const int r0 = row0 + wm * 32 + mt * 16 + qr;
#pragma unroll
        for (int nt = 0; nt < 8; nt++) {
            const int c = col0 + wn * 64 + nt * 8 + qk * 2;
            const float2 bv = *(const float2*)&bias[c];
            float v0 = acc[mt][nt][0] + bv.x;
            float v1 = acc[mt][nt][1] + bv.y;
            float v2 = acc[mt][nt][2] + bv.x;
            float v3 = acc[mt][nt][3] + bv.y;
            if (act) {
                v0 = 1.0f / (1.0f + __expf(-v0));
                v1 = 1.0f / (1.0f + __expf(-v1));
                v2 = 1.0f / (1.0f + __expf(-v2));
                v3 = 1.0f / (1.0f + __expf(-v3));
            }
            *(float2*)&C[(size_t)r0 * Nn + c]       = make_float2(v0, v1);
            *(float2*)&C[(size_t)(r0 + 8) * Nn + c] = make_float2(v2, v3);
        }
    }
}

// ---------------------------------------------------------------------------
// Block-cooperative attention. Block = 16 consecutive queries x 1 head,
// 512 threads (16 warps).
//   window rows (224): dense [n0-64, n0+15] (80) + 9 dyadic 16-row windows.
//   1) stage K window (tf32) + Q (tf32, pre-scaled) into smem, coalesced
//   2) scores for all 16x224 pairs via mma.m16n8k8 -> Ssh
//   3) warp w = query w: softmax over its 74 valid scores (+pos_bias from
//      smem), weights written back to Ssh, dim-parallel V sum + gate fuse
// ---------------------------------------------------------------------------
#define QT 16
#define NDENSE 65
#define WROWS 224          // 80 + 16*9
#define NTILES 28          // WROWS / 8
#define KLD 68             // K/Q smem row stride (words): 4*qr+qk banks distinct
#define SLD 228            // score row stride (words)

// dynamic smem layout (words):
//   Qsh  [16*KLD]      @ 0
//   Ksh  [224*KLD]     @ 1088
//   Ssh  [16*SLD]      @ 16320
//   pb   [80]          @ 19968
//   goff [80] (int)    @ 20048
//   gidx [224] (int)   @ 20128  -> total 20352 words = 81408 B
#define ATTN_SMEM_BYTES 81408

__global__ __launch_bounds__(512, 2)
void attn_kernel(const float* __restrict__ qkv, const float* __restrict__ gate,
                 const float* __restrict__ pos_bias, const int* __restrict__ offsets,
                 float* __restrict__ attn_out, int NO)
{
    extern __shared__ __align__(16) float dsm[];
    float* Qsh  = dsm;
    float* Ksh  = dsm + 16 * KLD;
    float* Ssh  = dsm + 16 * KLD + WROWS * KLD;
    float* pb   = Ssh + 16 * SLD;
    int*   goff = (int*)(pb + 80);
    int*   gidx = goff + 80;

    const int tid = threadIdx.x;
    const int w = tid >> 5;
    const int l = tid & 31;
    const int h  = blockIdx.y;
    const int n0 = blockIdx.x * QT;

    // offsets + pos_bias row + gather indices
    if (tid < NO) {
        goff[tid] = offsets[tid];
        pb[tid]   = pos_bias[tid * NHEAD + h];
    }
    if (tid < WROWS) {
        int sn;
        if (tid < 80) sn = n0 - 64 + tid;
        else {
            const int g = (tid - 80) >> 4;
            const int s = (tid - 80) & 15;
            sn = (NDENSE + g < NO) ? (n0 - offsets[NDENSE + g] + s) : 0;
        }
        gidx[tid] = max(sn, 0);
    }
    __syncthreads();

    // stage K window (tf32-rounded) and Q (tf32, pre-scaled by HD^-0.5)
    const float* Kg = qkv + DMODEL + h * HDIM;
    for (int i = tid; i < WROWS * 16; i += 512) {
        const int r  = i >> 4;
        const int c4 = (i & 15) << 2;
        const float4 v = *(const float4*)(Kg + (size_t)gidx[r] * QKV_W + c4);
        *(float4*)(Ksh + r * KLD + c4) =
            make_float4(rna_tf32(v.x), rna_tf32(v.y), rna_tf32(v.z), rna_tf32(v.w));
    }
    const float* Qg = qkv + h * HDIM;
    if (tid < 256) {
        const int r  = tid >> 4;
        const int c4 = (tid & 15) << 2;
        const float4 v = *(const float4*)(Qg + (size_t)(n0 + r) * QKV_W + c4);
        *(float4*)(Qsh + r * KLD + c4) =
            make_float4(rna_tf32(v.x * 0.125f), rna_tf32(v.y * 0.125f),
                        rna_tf32(v.z * 0.125f), rna_tf32(v.w * 0.125f));
    }
    __syncthreads();

    // scores: 16 x 224 via mma, warp w handles n-tiles {w, w+16}
    const int qk = l & 3;
    const int qr = l >> 2;
    for (int nt = w; nt < NTILES; nt += 16) {
        float acc[4] = {0.0f, 0.0f, 0.0f, 0.0f};
#pragma unroll
        for (int ks = 0; ks < 8; ks++) {
            unsigned a[4], b[2];
            const float* qp = Qsh + qr * KLD + ks * 8 + qk;
            a[0] = __float_as_uint(qp[0]);
            a[1] = __float_as_uint(qp[8 * KLD]);
            a[2] = __float_as_uint(qp[4]);
            a[3] = __float_as_uint(qp[8 * KLD + 4]);
            const float* kp = Ksh + (nt * 8 + qr) * KLD + ks * 8 + qk;
            b[0] = __float_as_uint(kp[0]);
            b[1] = __float_as_uint(kp[4]);
            mma16n8k8(acc, a, b);
        }
        *(float2*)(Ssh + qr * SLD + nt * 8 + 2 * qk)       = make_float2(acc[0], acc[1]);
        *(float2*)(Ssh + (qr + 8) * SLD + nt * 8 + 2 * qk) = make_float2(acc[2], acc[3]);
    }
    __syncthreads();

    // per-warp softmax + V accumulation; warp w = query n0+w
    const int n = n0 + w;
    float sloc[3];
    float m = -CUDART_INF_F;
#pragma unroll
    for (int j = 0; j < 3; j++) {
        const int o = l + 32 * j;
        float s = -CUDART_INF_F;
        if (o < NO) {
            const int off = goff[o];
            if (n - off >= 0) {
                const int col = (o < NDENSE) ? (w + 64 - off)
                                             : (80 + ((o - NDENSE) << 4) + w);
                s = Ssh[w * SLD + col] + pb[o];
            }
        }
        sloc[j] = s;
        m = fmaxf(m, s);
    }
#pragma unroll
    for (int off = 16; off > 0; off >>= 1)
        m = fmaxf(m, __shfl_xor_sync(0xFFFFFFFFu, m, off));

    float ssum = 0.0f;
    float eloc[3];
#pragma unroll
    for (int j = 0; j < 3; j++) {
        const float e = (sloc[j] == -CUDART_INF_F) ? 0.0f : __expf(sloc[j] - m);
        eloc[j] = e;
        ssum += e;
    }
#pragma unroll
    for (int off = 16; off > 0; off >>= 1)
        ssum += __shfl_xor_sync(0xFFFFFFFFu, ssum, off);

    const float inv = 1.0f / ssum;
#pragma unroll
    for (int j = 0; j < 3; j++) {
        const int o = l + 32 * j;
        if (o < NO) {
            const int off = goff[o];
            const int col = (o < NDENSE) ? (w + 64 - off)
                                         : (80 + ((o - NDENSE) << 4) + w);
            Ssh[w * SLD + col] = eloc[j] * inv;   // 0 when invalid
        }
    }
    __syncwarp();

    float ax = 0.0f, ay = 0.0f;
    const float* Vg = qkv + 2 * DMODEL + h * HDIM;
    for (int o = 0; o < NO; o++) {
        const int off = goff[o];
        const int col = (o < NDENSE) ? (w + 64 - off)
                                     : (80 + ((o - NDENSE) << 4) + w);
        const float a = Ssh[w * SLD + col];
        int idx = n - off;
        if (idx < 0) idx = 0;
        const float2 v2 = *(const float2*)(Vg + (size_t)idx * QKV_W + 2 * l);
        ax += a * v2.x;
        ay += a * v2.y;
    }

    const int colo = h * HDIM + 2 * l;
    const float2 g = *(const float2*)(gate + (size_t)n * DMODEL + colo);
    float2 r;
    r.x = rna_tf32(ax * g.x);
    r.y = rna_tf32(ay * g.y);
    *(float2*)(attn_out + (size_t)n * DMODEL + colo) = r;
}

// ---------------------------------------------------------------------------
// Launch
// ---------------------------------------------------------------------------
extern "C" void kernel_launch(void* const* d_in, const int* in_sizes, int n_in,
                              void* d_out, int out_size)
{
    const float* x        = (const float*)d_in[0];
    const float* Wqkv     = (const float*)d_in[1];
    const float* bqkv     = (const float*)d_in[2];
    const float* Wgate    = (const float*)d_in[3];
    const float* bgate    = (const float*)d_in[4];
    const float* Wout     = (const float*)d_in[5];
    const float* bout     = (const float*)d_in[6];
    const float* pos_bias = (const float*)d_in[7];
    const int*   offsets  = (const int*)d_in[8];
    const int NO = in_sizes[8];

    float *qkv_p, *gate_p, *attn_p, *xr_p, *wqkvr_p, *wgatr_p, *woutr_p;
    cudaGetSymbolAddress((void**)&qkv_p,   g_qkv);
    cudaGetSymbolAddress((void**)&gate_p,  g_gate);
    cudaGetSymbolAddress((void**)&attn_p,  g_attn);
    cudaGetSymbolAddress((void**)&xr_p,    g_xr);
    cudaGetSymbolAddress((void**)&wqkvr_p, g_wqkvr);
    cudaGetSymbolAddress((void**)&wgatr_p, g_wgatr);
    cudaGetSymbolAddress((void**)&woutr_p, g_woutr);

    cudaFuncSetAttribute(attn_kernel, cudaFuncAttributeMaxDynamicSharedMemorySize,
                         ATTN_SMEM_BYTES);

    // 0) tf32-round all GEMM operands in one pass
    round_all<<<1184, 256>>>((const float4*)x,     (float4*)xr_p,
                             (const float4*)Wqkv,  (float4*)wqkvr_p,
                             (const float4*)Wgate, (float4*)wgatr_p,
                             (const float4*)Wout,  (float4*)woutr_p);

    // 1) qkv = x @ Wqkv^T + bqkv
    mma_gemm<<<dim3(QKV_W / BN, NSEQ / BM), 256>>>(
        xr_p, wqkvr_p, bqkv, qkv_p, NSEQ, QKV_W, DMODEL, 0);

    // 2) gate = sigmoid(x @ Wgate^T + bgate)
    mma_gemm<<<dim3(DMODEL / BN, NSEQ / BM), 256>>>(
        xr_p, wgatr_p, bgate, gate_p, NSEQ, DMODEL, DMODEL, 1);

    // 3) attention + gate multiply (tf32-rounded output)
    attn_kernel<<<dim3(NSEQ / QT, NHEAD), 512, ATTN_SMEM_BYTES>>>(
        qkv_p, gate_p, pos_bias, offsets, attn_p, NO);

    // 4) out = (attn*gate) @ Wout^T + bout
    mma_gemm<<<dim3(DMODEL / BN, NSEQ / BM), 256>>>(
        attn_p, woutr_p, bout, (float*)d_out, NSEQ, DMODEL, DMODEL, 0);
}

// round 10
// speedup vs baseline: 1.5385x; 1.1045x over previous
#include <cuda_runtime.h>
#include <cuda_bf16.h>
#include <math_constants.h>

// Problem constants
#define NSEQ 2048
#define DMODEL 1024
#define NHEAD 16
#define HDIM 64
#define QKV_W (3 * DMODEL)   // 3072
#define QG_W  (4 * DMODEL)   // 4096 (qkv || gate fused weight rows)

// ---------------------------------------------------------------------------
// Scratch (__device__ globals; no allocations allowed)
// ---------------------------------------------------------------------------
__device__ float g_qkv [NSEQ * QKV_W];     // q|k|v, fp32
__device__ float g_gate[NSEQ * DMODEL];    // sigmoid(x Wg^T + bg), fp32
__device__ float g_attn[NSEQ * DMODEL];    // (attn*gate), tf32-rounded
__device__ float g_xr  [NSEQ * DMODEL];    // tf32-rounded x
__device__ float g_wqg [QG_W * DMODEL];    // tf32-rounded [Wqkv ; Wgate]
__device__ float g_woutr[DMODEL * DMODEL]; // tf32-rounded Wout

__device__ __forceinline__ float rna_tf32(float x) {
    float y;
    asm("cvt.rna.tf32.f32 %0, %1;" : "=f"(y) : "f"(x));
    return y;
}

__device__ __forceinline__ void mma16n8k8(float* c, const unsigned* a, const unsigned* b)
{
    asm volatile(
        "mma.sync.aligned.m16n8k8.row.col.f32.tf32.tf32.f32 "
        "{%0,%1,%2,%3}, {%4,%5,%6,%7}, {%8,%9}, {%0,%1,%2,%3};\n"
        : "+f"(c[0]), "+f"(c[1]), "+f"(c[2]), "+f"(c[3])
        : "r"(a[0]), "r"(a[1]), "r"(a[2]), "r"(a[3]), "r"(b[0]), "r"(b[1]));
}

// ---------------------------------------------------------------------------
// Single merged tf32-rounding pass: x, Wqkv -> g_wqg[0:], Wgate -> g_wqg[3072*K:],
// Wout -> g_woutr
// ---------------------------------------------------------------------------
#define RN0 (NSEQ * DMODEL / 4)
#define RN1 (QKV_W * DMODEL / 4)
#define RN2 (DMODEL * DMODEL / 4)
#define RN3 (DMODEL * DMODEL / 4)

__global__ void round_all(const float4* __restrict__ x,  float4* __restrict__ xr,
                          const float4* __restrict__ wq, float4* __restrict__ wqr,
                          const float4* __restrict__ wg, float4* __restrict__ wgr,
                          const float4* __restrict__ wo, float4* __restrict__ wor)
{
    const int total = RN0 + RN1 + RN2 + RN3;
    int i = blockIdx.x * blockDim.x + threadIdx.x;
    const int stride = gridDim.x * blockDim.x;
    for (; i < total; i += stride) {
        const float4* src; float4* dst; int j = i;
        if (j < RN0)              { src = x;  dst = xr; }
        else if ((j -= RN0) < RN1){ src = wq; dst = wqr; }
        else if ((j -= RN1) < RN2){ src = wg; dst = wgr; }
        else { j -= RN2;            src = wo; dst = wor; }
        float4 v = src[j];
        v.x = rna_tf32(v.x); v.y = rna_tf32(v.y);
        v.z = rna_tf32(v.z); v.w = rna_tf32(v.w);
        dst[j] = v;
    }
}

// ---------------------------------------------------------------------------
// tf32 tensor-core GEMM, 64x64 warp tiles (1.0 LDS/MMA):
//   C = A @ Wcat^T + bias, logical Nn = gridDim.x*128 over concatenated cols.
//   Blocks with col0 <  split -> C0 (row stride N0), bias0, no activation
//   Blocks with col0 >= split -> C1 (row stride N1), bias1, sigmoid
// 128x128 CTA tile, 4 warps (2x2 of 64x64), BK=16, double-buffered cp.async.
// ---------------------------------------------------------------------------
#define BM 128
#define BN 128
#define BKT 16
#define LDSD 20

#define CP16(sm, gp) \
    asm volatile("cp.async.cg.shared.global [%0], [%1], 16;\n" :: "r"(sm), "l"(gp) : "memory")

__global__ __launch_bounds__(128, 2)
void mma_gemm(const float* __restrict__ A, const float* __restrict__ Wcat,
              const float* __restrict__ bias0, float* __restrict__ C0, int N0,
              const float* __restrict__ bias1, float* __restrict__ C1, int N1,
              int K, int split)
{
    __shared__ __align__(16) unsigned As[2][BM * LDSD];
    __shared__ __align__(16) unsigned Bs[2][BN * LDSD];

    const int tid  = threadIdx.x;
    const int lane = tid & 31;
    const int wid  = tid >> 5;
    const int wm   = wid & 1;          // 2 warps along M (64 rows each)
    const int wn   = wid >> 1;         // 2 warps along N (64 cols each)
    const int row0 = blockIdx.y * BM;
    const int col0 = blockIdx.x * BN;

    // copy mapping: 128 threads x 4 rows apart; 4 float4 per operand per thread
    const int cpr = tid >> 2;          // 0..31
    const int cpc = (tid & 3) * 4;     // 0,4,8,12

    const float* Ag = A    + (size_t)(row0 + cpr) * K + cpc;
    const float* Wg = Wcat + (size_t)(col0 + cpr) * K + cpc;

    unsigned sA[2], sB[2];
    sA[0] = (unsigned)__cvta_generic_to_shared(&As[0][cpr * LDSD + cpc]);
    sA[1] = (unsigned)__cvta_generic_to_shared(&As[1][cpr * LDSD + cpc]);
    sB[0] = (unsigned)__cvta_generic_to_shared(&Bs[0][cpr * LDSD + cpc]);
    sB[1] = (unsigned)__cvta_generic_to_shared(&Bs[1][cpr * LDSD + cpc]);
    const unsigned soff32 = 32 * LDSD * 4;   // +32 rows in smem (bytes)
    const size_t   goff32 = (size_t)32 * K;  // +32 rows in gmem (elems)

    float acc[4][8][4];
#pragma unroll
    for (int mt = 0; mt < 4; mt++)
#pragma unroll
        for (int nt = 0; nt < 8; nt++)
#pragma unroll
            for (int i = 0; i < 4; i++) acc[mt][nt][i] = 0.0f;

    const int T = K / BKT;

    // prologue: tile 0 -> buf 0
#pragma unroll
    for (int r = 0; r < 4; r++) {
        CP16(sA[0] + r * soff32, Ag + r * goff32);
        CP16(sB[0] + r * soff32, Wg + r * goff32);
    }
    asm volatile("cp.async.commit_group;\n" ::: "memory");

    const int qk = lane & 3;
    const int qr = lane >> 2;

    for (int t = 0; t < T; t++) {
        const int buf = t & 1;
        if (t + 1 < T) {
            const int nb = buf ^ 1;
            const int k1 = (t + 1) * BKT;
#pragma unroll
            for (int r = 0; r < 4; r++) {
                CP16(sA[nb] + r * soff32, Ag + k1 + r * goff32);
                CP16(sB[nb] + r * soff32, Wg + k1 + r * goff32);
            }
        }
        asm volatile("cp.async.commit_group;\n" ::: "memory");
        asm volatile("cp.async.wait_group 1;\n" ::: "memory");
        __syncthreads();

        const unsigned* as = As[buf];
        const unsigned* bs = Bs[buf];
#pragma unroll
        for (int ks = 0; ks < 2; ks++) {
            unsigned bfr[8][2];
#pragma unroll
            for (int nt = 0; nt < 8; nt++) {
                const int n = wn * 64 + nt * 8 + qr;
                bfr[nt][0] = bs[n * LDSD + ks * 8 + qk];
                bfr[nt][1] = bs[n * LDSD + ks * 8 + qk + 4];
            }
            unsigned afr[4][4];
#pragma unroll
            for (int mt = 0; mt < 4; mt++) {
                const int m = wm * 64 + mt * 16 + qr;
                afr[mt][0] = as[m * LDSD + ks * 8 + qk];
                afr[mt][1] = as[(m + 8) * LDSD + ks * 8 + qk];
                afr[mt][2] = as[m * LDSD + ks * 8 + qk + 4];
                afr[mt][3] = as[(m + 8) * LDSD + ks * 8 + qk + 4];
            }
#pragma unroll
            for (int mt = 0; mt < 4; mt++)
#pragma unroll
                for (int nt = 0; nt < 8; nt++)
                    mma16n8k8(acc[mt][nt], afr[mt], bfr[nt]);
        }
        __syncthreads();
    }

    // epilogue: route to the right output (block-uniform)
    const int second = (col0 >= split);
    const float* bias = second ? bias1 : bias0;
    float* C  = second ? C1 : C0;
    const int Nn = second ? N1 : N0;
    const int cb = col0 - (second ? split : 0);

#pragma unroll
    for (int mt = 0; mt < 4; mt++) {
        const int r0 = row0 + wm * 64 + mt * 16 + qr;
#pragma unroll
        for (int nt = 0; nt < 8; nt++) {
            const int c = cb + wn * 64 + nt * 8 + qk * 2;
            const float2 bv = *(const float2*)&bias[c];
            float v0 = acc[mt][nt][0] + bv.x;
            float v1 = acc[mt][nt][1] + bv.y;
            float v2 = acc[mt][nt][2] + bv.x;
            float v3 = acc[mt][nt][3] + bv.y;
            if (second) {
                v0 = 1.0f / (1.0f + __expf(-v0));
                v1 = 1.0f / (1.0f + __expf(-v1));
                v2 = 1.0f / (1.0f + __expf(-v2));
                v3 = 1.0f / (1.0f + __expf(-v3));
            }
            *(float2*)&C[(size_t)r0 * Nn + c]       = make_float2(v0, v1);
            *(float2*)&C[(size_t)(r0 + 8) * Nn + c] = make_float2(v2, v3);
        }
    }
}

// ---------------------------------------------------------------------------
// Block-cooperative attention. Block = 16 consecutive queries x 1 head,
// 512 threads (16 warps). Score via mma over a 224-row staged K window,
// per-warp softmax, dim-parallel V sum + gate fuse.
// ---------------------------------------------------------------------------
#define QT 16
#define NDENSE 65
#define WROWS 224          // 80 dense + 16*9 dyadic
#define NTILES 28
#define KLD 68
#define SLD 228

// dyn smem (words): Qsh 16*68 | Ksh 224*68 | Ssh 16*228 | pb 80 | goff 80 |
//                   base 80 | gidx 224  => 20432 words = 81728 B
#define ATTN_SMEM_BYTES 81728

__global__ __launch_bounds__(512, 2)
void attn_kernel(const float* __restrict__ qkv, const float* __restrict__ gate,
                 const float* __restrict__ pos_bias, const int* __restrict__ offsets,
                 float* __restrict__ attn_out, int NO)
{
    extern __shared__ __align__(16) float dsm[];
    float* Qsh  = dsm;
    float* Ksh  = dsm + 16 * KLD;
    float* Ssh  = dsm + 16 * KLD + WROWS * KLD;
    float* pb   = Ssh + 16 * SLD;
    int*   goff = (int*)(pb + 80);
    int*   base = goff + 80;
    int*   gidx = base + 80;

    const int tid = threadIdx.x;
    const int w = tid >> 5;
    const int l = tid & 31;
    const int h  = blockIdx.y;
    const int n0 = blockIdx.x * QT;

    if (tid < NO) {
        const int off = offsets[tid];
        goff[tid] = off;
        pb[tid]   = pos_bias[tid * NHEAD + h];
        base[tid] = (tid < NDENSE) ? (64 - off) : (80 + ((tid - NDENSE) << 4));
    }
    if (tid < WROWS) {
        int sn;
        if (tid < 80) sn = n0 - 64 + tid;
        else {
            const int g = (tid - 80) >> 4;
            const int s = (tid - 80) & 15;
            sn = (NDENSE + g < NO) ? (n0 - offsets[NDENSE + g] + s) : 0;
        }
        gidx[tid] = max(sn, 0);
    }
    __syncthreads();

    // stage K window (tf32) and Q (tf32, pre-scaled by HD^-0.5)
    const float* Kg = qkv + DMODEL + h * HDIM;
    for (int i = tid; i < WROWS * 16; i += 512) {
        const int r  = i >> 4;
        const int c4 = (i & 15) << 2;
        const float4 v = *(const float4*)(Kg + (size_t)gidx[r] * QKV_W + c4);
        *(float4*)(Ksh + r * KLD + c4) =
            make_float4(rna_tf32(v.x), rna_tf32(v.y), rna_tf32(v.z), rna_tf32(v.w));
    }
    const float* Qg = qkv + h * HDIM;
    if (tid < 256) {
        const int r  = tid >> 4;
        const int c4 = (tid & 15) << 2;
        const float4 v = *(const float4*)(Qg + (size_t)(n0 + r) * QKV_W + c4);
        *(float4*)(Qsh + r * KLD + c4) =
            make_float4(rna_tf32(v.x * 0.125f), rna_tf32(v.y * 0.125f),
                        rna_tf32(v.z * 0.125f), rna_tf32(v.w * 0.125f));
    }
    __syncthreads();

    // scores: 16 x 224 via mma, warp w handles n-tiles {w, w+16}
    const int qk = l & 3;
    const int qr = l >> 2;
    for (int nt = w; nt < NTILES; nt += 16) {
        float acc[4] = {0.0f, 0.0f, 0.0f, 0.0f};
#pragma unroll
        for (int ks = 0; ks < 8; ks++) {
            unsigned a[4], b[2];
            const float* qp = Qsh + qr * KLD + ks * 8 + qk;
            a[0] = __float_as_uint(qp[0]);
            a[1] = __float_as_uint(qp[8 * KLD]);
            a[2] = __float_as_uint(qp[4]);
            a[3] = __float_as_uint(qp[8 * KLD + 4]);
            const float* kp = Ksh + (nt * 8 + qr) * KLD + ks * 8 + qk;
            b[0] = __float_as_uint(kp[0]);
            b[1] = __float_as_uint(kp[4]);
            mma16n8k8(acc, a, b);
        }
        *(float2*)(Ssh + qr * SLD + nt * 8 + 2 * qk)       = make_float2(acc[0], acc[1]);
        *(float2*)(Ssh + (qr + 8) * SLD + nt * 8 + 2 * qk) = make_float2(acc[2], acc[3]);
    }
    __syncthreads();

    // per-warp softmax; warp w = query n0+w
    const int n = n0 + w;
    float* Srow = Ssh + w * SLD;
    float sloc[3];
    float m = -CUDART_INF_F;
#pragma unroll
    for (int j = 0; j < 3; j++) {
        const int o = l + 32 * j;
        float s = -CUDART_INF_F;
        if (o < NO && n - goff[o] >= 0)
            s = Srow[base[o] + w] + pb[o];
        sloc[j] = s;
        m = fmaxf(m, s);
    }
#pragma unroll
    for (int off = 16; off > 0; off >>= 1)
        m = fmaxf(m, __shfl_xor_sync(0xFFFFFFFFu, m, off));

    float ssum = 0.0f;
    float eloc[3];
#pragma unroll
    for (int j = 0; j < 3; j++) {
        const float e = (sloc[j] == -CUDART_INF_F) ? 0.0f : __expf(sloc[j] - m);
        eloc[j] = e;
        ssum += e;
    }
#pragma unroll
    for (int off = 16; off > 0; off >>= 1)
        ssum += __shfl_xor_sync(0xFFFFFFFFu, ssum, off);

    const float inv = 1.0f / ssum;
#pragma unroll
    for (int j = 0; j < 3; j++) {
        const int o = l + 32 * j;
        if (o < NO) Srow[base[o] + w] = eloc[j] * inv;   // 0 when invalid
    }
    __syncwarp();

    // V accumulation (dim-parallel, lane covers dims 2l,2l+1)
    float ax = 0.0f, ay = 0.0f;
    const float* Vg = qkv + 2 * DMODEL + h * HDIM + 2 * l;
    for (int o = 0; o < NO; o++) {
        const float a = Srow[base[o] + w];
        int idx = n - goff[o];
        if (idx < 0) idx = 0;
        const float2 v2 = *(const float2*)(Vg + (size_t)idx * QKV_W);
        ax += a * v2.x;
        ay += a * v2.y;
    }

    const int colo = h * HDIM + 2 * l;
    const float2 g = *(const float2*)(gate + (size_t)n * DMODEL + colo);
    float2 r;
    r.x = rna_tf32(ax * g.x);
    r.y = rna_tf32(ay * g.y);
    *(float2*)(attn_out + (size_t)n * DMODEL + colo) = r;
}

// ---------------------------------------------------------------------------
// Launch
// ---------------------------------------------------------------------------
extern "C" void kernel_launch(void* const* d_in, const int* in_sizes, int n_in,
                              void* d_out, int out_size)
{
    const float* x        = (const float*)d_in[0];
    const float* Wqkv     = (const float*)d_in[1];
    const float* bqkv     = (const float*)d_in[2];
    const float* Wgate    = (const float*)d_in[3];
    const float* bgate    = (const float*)d_in[4];
    const float* Wout     = (const float*)d_in[5];
    const float* bout     = (const float*)d_in[6];
    const float* pos_bias = (const float*)d_in[7];
    const int*   offsets  = (const int*)d_in[8];
    const int NO = in_sizes[8];

    float *qkv_p, *gate_p, *attn_p, *xr_p, *wqg_p, *woutr_p;
    cudaGetSymbolAddress((void**)&qkv_p,   g_qkv);
    cudaGetSymbolAddress((void**)&gate_p,  g_gate);
    cudaGetSymbolAddress((void**)&attn_p,  g_attn);
    cudaGetSymbolAddress((void**)&xr_p,    g_xr);
    cudaGetSymbolAddress((void**)&wqg_p,   g_wqg);
    cudaGetSymbolAddress((void**)&woutr_p, g_woutr);

    cudaFuncSetAttribute(attn_kernel, cudaFuncAttributeMaxDynamicSharedMemorySize,
                         ATTN_SMEM_BYTES);

    // 0) tf32-round all GEMM operands (Wqkv||Wgate concatenated into g_wqg)
    round_all<<<1184, 256>>>((const float4*)x,     (float4*)xr_p,
                             (const float4*)Wqkv,  (float4*)wqg_p,
                             (const float4*)Wgate, (float4*)(wqg_p + (size_t)QKV_W * DMODEL),
                             (const float4*)Wout,  (float4*)woutr_p);

    // 1) fused: qkv = x@Wqkv^T+bqkv  AND  gate = sigmoid(x@Wgate^T+bgate)
    mma_gemm<<<dim3(QG_W / BN, NSEQ / BM), 128>>>(
        xr_p, wqg_p,
        bqkv,  qkv_p,  QKV_W,
        bgate, gate_p, DMODEL,
        DMODEL, QKV_W);

    // 2) attention + gate multiply (tf32-rounded output)
    attn_kernel<<<dim3(NSEQ / QT, NHEAD), 512, ATTN_SMEM_BYTES>>>(
        qkv_p, gate_p, pos_bias, offsets, attn_p, NO);

    // 3) out = (attn*gate) @ Wout^T + bout
    mma_gemm<<<dim3(DMODEL / BN, NSEQ / BM), 128>>>(
        attn_p, woutr_p,
        bout, (float*)d_out, DMODEL,
        bout, (float*)d_out, DMODEL,
        DMODEL, DMODEL * 2);
}

// round 11
// speedup vs baseline: 1.5502x; 1.0076x over previous
#include <cuda_runtime.h>
#include <cuda_bf16.h>
#include <math_constants.h>

// Problem constants
#define NSEQ 2048
#define DMODEL 1024
#define NHEAD 16
#define HDIM 64
#define QKV_W (3 * DMODEL)   // 3072
#define QG_W  (4 * DMODEL)   // 4096

// ---------------------------------------------------------------------------
// Scratch (__device__ globals; no allocations allowed)
// ---------------------------------------------------------------------------
__device__ float g_qkv [NSEQ * QKV_W];     // q|k|v, fp32
__device__ float g_gate[NSEQ * DMODEL];    // sigmoid(x Wg^T + bg), fp32
__device__ float g_attn[NSEQ * DMODEL];    // attn_out * gate, fp32

__device__ __forceinline__ float rna_tf32(float x) {
    float y;
    asm("cvt.rna.tf32.f32 %0, %1;" : "=f"(y) : "f"(x));
    return y;
}

__device__ __forceinline__ void mma16n8k8(float* c, const unsigned* a, const unsigned* b)
{
    asm volatile(
        "mma.sync.aligned.m16n8k8.row.col.f32.tf32.tf32.f32 "
        "{%0,%1,%2,%3}, {%4,%5,%6,%7}, {%8,%9}, {%0,%1,%2,%3};\n"
        : "+f"(c[0]), "+f"(c[1]), "+f"(c[2]), "+f"(c[3])
        : "r"(a[0]), "r"(a[1]), "r"(a[2]), "r"(a[3]), "r"(b[0]), "r"(b[1]));
}

// rna-round an smem word loaded as raw fp32 bits -> tf32 operand
#define LDR(x) __float_as_uint(rna_tf32(__uint_as_float(x)))

// ---------------------------------------------------------------------------
// tf32 tensor-core GEMM, in-kernel tf32 rounding of BOTH operands.
//   C = A @ Wsel^T + bias; blocks with col0 < split use W0/bias0/C0 (linear),
//   blocks with col0 >= split use W1/bias1/C1 (sigmoid epilogue).
// 128x128 CTA tile, 4 warps (2x2 of 64x64), BK=16, 3-stage cp.async ring,
// ONE __syncthreads per k-iter. Dynamic smem: 3 * 5120 words = 61440 B.
// ---------------------------------------------------------------------------
#define BM 128
#define BN 128
#define BKT 16
#define LDSD 20
#define STGW ((BM + BN) * LDSD)          // 5120 words / stage
#define GEMM_SMEM_BYTES (3 * STGW * 4)   // 61440

#define CP16(sm, gp) \
    asm volatile("cp.async.cg.shared.global [%0], [%1], 16;\n" :: "r"(sm), "l"(gp) : "memory")
#define CP_COMMIT() asm volatile("cp.async.commit_group;\n" ::: "memory")
#define CP_WAIT1()  asm volatile("cp.async.wait_group 1;\n" ::: "memory")

__global__ __launch_bounds__(128, 2)
void mma_gemm(const float* __restrict__ A,
              const float* __restrict__ W0, const float* __restrict__ bias0,
              float* __restrict__ C0, int N0,
              const float* __restrict__ W1, const float* __restrict__ bias1,
              float* __restrict__ C1, int N1,
              int K, int split)
{
    extern __shared__ __align__(16) unsigned gsm[];

    const int tid  = threadIdx.x;
    const int lane = tid & 31;
    const int wid  = tid >> 5;
    const int wm   = wid & 1;
    const int wn   = wid >> 1;
    const int row0 = blockIdx.y * BM;
    const int col0 = blockIdx.x * BN;

    const int second = (col0 >= split);
    const float* Wsel = second ? W1 : W0;
    const int colL = col0 - (second ? split : 0);

    const int cpr = tid >> 2;          // 0..31
    const int cpc = (tid & 3) * 4;     // 0,4,8,12

    const float* Ag = A    + (size_t)(row0 + cpr) * K + cpc;
    const float* Wg = Wsel + (size_t)(colL + cpr) * K + cpc;

    const unsigned shbase = (unsigned)__cvta_generic_to_shared(gsm);
    const unsigned aoff = (cpr * LDSD + cpc) * 4;
    const unsigned boff = (BM * LDSD + cpr * LDSD + cpc) * 4;
    const unsigned soff32 = 32 * LDSD * 4;
    const size_t   goff32 = (size_t)32 * K;

    float acc[4][8][4];
#pragma unroll
    for (int mt = 0; mt < 4; mt++)
#pragma unroll
        for (int nt = 0; nt < 8; nt++)
#pragma unroll
            for (int i = 0; i < 4; i++) acc[mt][nt][i] = 0.0f;

    const int T = K / BKT;

    // prologue: stages 0 and 1
#pragma unroll
    for (int s = 0; s < 2; s++) {
        const unsigned sb = shbase + s * STGW * 4;
#pragma unroll
        for (int r = 0; r < 4; r++) {
            CP16(sb + aoff + r * soff32, Ag + s * BKT + r * goff32);
            CP16(sb + boff + r * soff32, Wg + s * BKT + r * goff32);
        }
        CP_COMMIT();
    }

    const int qk = lane & 3;
    const int qr = lane >> 2;

    int cur = 0;           // slot of stage t
    int nxt = 2;           // slot of stage t+2
    for (int t = 0; t < T; t++) {
        CP_WAIT1();            // stage t arrived (stage t+1 may be in flight)
        __syncthreads();       // all warps done reading stage t-1 -> slot nxt free

        if (t + 2 < T) {
            const unsigned sb = shbase + nxt * STGW * 4;
            const int k2 = (t + 2) * BKT;
#pragma unroll
            for (int r = 0; r < 4; r++) {
                CP16(sb + aoff + r * soff32, Ag + k2 + r * goff32);
                CP16(sb + boff + r * soff32, Wg + k2 + r * goff32);
            }
        }
        CP_COMMIT();

        const unsigned* as = gsm + cur * STGW;
        const unsigned* bs = as + BM * LDSD;
#pragma unroll
        for (int ks = 0; ks < 2; ks++) {
            unsigned bfr[8][2];
#pragma unroll
            for (int nt = 0; nt < 8; nt++) {
                const int n = wn * 64 + nt * 8 + qr;
                bfr[nt][0] = LDR(bs[n * LDSD + ks * 8 + qk]);
                bfr[nt][1] = LDR(bs[n * LDSD + ks * 8 + qk + 4]);
            }
            unsigned afr[4][4];
#pragma unroll
            for (int mt = 0; mt < 4; mt++) {
                const int m = wm * 64 + mt * 16 + qr;
                afr[mt][0] = LDR(as[m * LDSD + ks * 8 + qk]);
                afr[mt][1] = LDR(as[(m + 8) * LDSD + ks * 8 + qk]);
                afr[mt][2] = LDR(as[m * LDSD + ks * 8 + qk + 4]);
                afr[mt][3] = LDR(as[(m + 8) * LDSD + ks * 8 + qk + 4]);
            }
#pragma unroll
            for (int mt = 0; mt < 4; mt++)
#pragma unroll
                for (int nt = 0; nt < 8; nt++)
                    mma16n8k8(acc[mt][nt], afr[mt], bfr[nt]);
        }
        cur = (cur == 2) ? 0 : cur + 1;
        nxt = (nxt == 2) ? 0 : nxt + 1;
    }

    // epilogue
    const float* bias = second ? bias1 : bias0;
    float* C  = second ? C1 : C0;
    const int Nn = second ? N1 : N0;

#pragma unroll
    for (int mt = 0; mt < 4; mt++) {
        const int r0 = row0 + wm * 64 + mt * 16 + qr;
#pragma unroll
        for (int nt = 0; nt < 8; nt++) {
            const int c = colL + wn * 64 + nt * 8 + qk * 2;
            const float2 bv = *(const float2*)&bias[c];
            float v0 = acc[mt][nt][0] + bv.x;
            float v1 = acc[mt][nt][1] + bv.y;
            float v2 = acc[mt][nt][2] + bv.x;
            float v3 = acc[mt][nt][3] + bv.y;
            if (second) {
                v0 = 1.0f / (1.0f + __expf(-v0));
                v1 = 1.0f / (1.0f + __expf(-v1));
                v2 = 1.0f / (1.0f + __expf(-v2));
                v3 = 1.0f / (1.0f + __expf(-v3));
            }
            *(float2*)&C[(size_t)r0 * Nn + c]       = make_float2(v0, v1);
            *(float2*)&C[(size_t)(r0 + 8) * Nn + c] = make_float2(v2, v3);
        }
    }
}

// ---------------------------------------------------------------------------
// Block-cooperative attention, fully tensor-core:
//   block = 16 consecutive queries x 1 head, 512 threads (16 warps)
//   1) stage Q (rna, pre-scaled), K window (rna), gate (raw) into smem
//   2) scores 16x224 via mma -> Ssh
//   3) restage V into K's buffer (rna); per-warp softmax on raw scores,
//      zero own score row, scatter normalized weights (rna)
//   4) P@V via mma: warp w -> n-tile w&7, k-half w>>3; smem partial reduce;
//      gate multiply; store
// ---------------------------------------------------------------------------
#define QT 16
#define NDENSE 65
#define WROWS 224
#define NTILES 28
#define KLD 68
#define SLD 228

// smem layout (words):
//   Qsh/Psh 16*68=1088 @0 | Ksh/Vsh 224*68=15232 @1088 | Ssh 16*228=3648 @16320
//   Gsh 16*68=1088 @19968 | pb 80 @21056 | goff 80 @21136 | base 80 @21216
//   gidx 224 @21296  -> 21520 words = 86080 B
#define ATTN_SMEM_BYTES 86080

__global__ __launch_bounds__(512, 2)
void attn_kernel(const float* __restrict__ qkv, const float* __restrict__ gate,
                 const float* __restrict__ pos_bias, const int* __restrict__ offsets,
                 float* __restrict__ attn_out, int NO)
{
    extern __shared__ __align__(16) float dsm[];
    float* Qsh  = dsm;                       // later: P@V partial buffer
    float* Ksh  = dsm + 1088;                // later: V window
    float* Ssh  = dsm + 16320;
    float* Gsh  = dsm + 19968;
    float* pb   = dsm + 21056;
    int*   goff = (int*)(dsm + 21136);
    int*   base = (int*)(dsm + 21216);
    int*   gidx = (int*)(dsm + 21296);

    const int tid = threadIdx.x;
    const int w = tid >> 5;
    const int l = tid & 31;
    const int h  = blockIdx.y;
    const int n0 = blockIdx.x * QT;

    if (tid < NO) {
        const int off = offsets[tid];
        goff[tid] = off;
        pb[tid]   = pos_bias[tid * NHEAD + h];
        base[tid] = (tid < NDENSE) ? (64 - off) : (80 + ((tid - NDENSE) << 4));
    }
    if (tid < WROWS) {
        int sn;
        if (tid < 80) sn = n0 - 64 + tid;
        else {
            const int g = (tid - 80) >> 4;
            const int s = (tid - 80) & 15;
            sn = (NDENSE + g < NO) ? (n0 - offsets[NDENSE + g] + s) : 0;
        }
        gidx[tid] = max(sn, 0);
    }
    __syncthreads();

    // stage K (rna), Q (rna, scaled), gate (raw)
    const float* Kg = qkv + DMODEL + h * HDIM;
    for (int i = tid; i < WROWS * 16; i += 512) {
        const int r  = i >> 4;
        const int c4 = (i & 15) << 2;
        const float4 v = *(const float4*)(Kg + (size_t)gidx[r] * QKV_W + c4);
        *(float4*)(Ksh + r * KLD + c4) =
            make_float4(rna_tf32(v.x), rna_tf32(v.y), rna_tf32(v.z), rna_tf32(v.w));
    }
    if (tid < 256) {
        const int r  = tid >> 4;
        const int c4 = (tid & 15) << 2;
        const float4 v = *(const float4*)(qkv + (size_t)(n0 + r) * QKV_W + h * HDIM + c4);
        *(float4*)(Qsh + r * KLD + c4) =
            make_float4(rna_tf32(v.x * 0.125f), rna_tf32(v.y * 0.125f),
                        rna_tf32(v.z * 0.125f), rna_tf32(v.w * 0.125f));
    } else {
        const int t2 = tid - 256;
        const int r  = t2 >> 4;
        const int c4 = (t2 & 15) << 2;
        *(float4*)(Gsh + r * KLD + c4) =
            *(const float4*)(gate + (size_t)(n0 + r) * DMODEL + h * HDIM + c4);
    }
    __syncthreads();

    // scores: 16 x 224 via mma; warp w handles n-tiles {w, w+16}
    const int qk = l & 3;
    const int qr = l >> 2;
    for (int nt = w; nt < NTILES; nt += 16) {
        float acc[4] = {0.0f, 0.0f, 0.0f, 0.0f};
#pragma unroll
        for (int ks = 0; ks < 8; ks++) {
            unsigned a[4], b[2];
            const float* qp = Qsh + qr * KLD + ks * 8 + qk;
            a[0] = __float_as_uint(qp[0]);
            a[1] = __float_as_uint(qp[8 * KLD]);
            a[2] = __float_as_uint(qp[4]);
            a[3] = __float_as_uint(qp[8 * KLD + 4]);
            const float* kp = Ksh + (nt * 8 + qr) * KLD + ks * 8 + qk;
            b[0] = __float_as_uint(kp[0]);
            b[1] = __float_as_uint(kp[4]);
            mma16n8k8(acc, a, b);
        }
        *(float2*)(Ssh + qr * SLD + nt * 8 + 2 * qk)       = make_float2(acc[0], acc[1]);
        *(float2*)(Ssh + (qr + 8) * SLD + nt * 8 + 2 * qk) = make_float2(acc[2], acc[3]);
    }
    __syncthreads();

    // restage V into Ksh (rna) — K data no longer needed
    const float* Vg = qkv + 2 * DMODEL + h * HDIM;
    for (int i = tid; i < WROWS * 16; i += 512) {
        const int r  = i >> 4;
        const int c4 = (i & 15) << 2;
        const float4 v = *(const float4*)(Vg + (size_t)gidx[r] * QKV_W + c4);
        *(float4*)(Ksh + r * KLD + c4) =
            make_float4(rna_tf32(v.x), rna_tf32(v.y), rna_tf32(v.z), rna_tf32(v.w));
    }

    // per-warp softmax on raw scores; warp w = query n0+w
    const int n = n0 + w;
    float* Srow = Ssh + w * SLD;
    float sloc[3];
    float m = -CUDART_INF_F;
#pragma unroll
    for (int j = 0; j < 3; j++) {
        const int o = l + 32 * j;
        float s = -CUDART_INF_F;
        if (o < NO && n - goff[o] >= 0)
            s = Srow[base[o] + w] + pb[o];
        sloc[j] = s;
        m = fmaxf(m, s);
    }
#pragma unroll
    for (int off = 16; off > 0; off >>= 1)
        m = fmaxf(m, __shfl_xor_sync(0xFFFFFFFFu, m, off));

    float ssum = 0.0f;
    float eloc[3];
#pragma unroll
    for (int j = 0; j < 3; j++) {
        const float e = (sloc[j] == -CUDART_INF_F) ? 0.0f : __expf(sloc[j] - m);
        eloc[j] = e;
        ssum += e;
    }
#pragma unroll
    for (int off = 16; off > 0; off >>= 1)
        ssum += __shfl_xor_sync(0xFFFFFFFFu, ssum, off);
    const float inv = 1.0f / ssum;

    // zero own score row, then scatter rna'd weights
#pragma unroll
    for (int j = 0; j < 7; j++) Srow[l + 32 * j] = 0.0f;
    __syncwarp();
#pragma unroll
    for (int j = 0; j < 3; j++) {
        const int o = l + 32 * j;
        if (o < NO) Srow[base[o] + w] = rna_tf32(eloc[j] * inv);
    }
    __syncthreads();   // V staged + all 16 rows weighted

    // P@V: out[16q][64d] = P[16][224] @ V[224][64]
    // warp w: n-tile = w&7 (8 dims), k-half = w>>3 (14 of 28 k-steps)
    const int nt2 = w & 7;
    const int kh  = w >> 3;
    float facc[4] = {0.0f, 0.0f, 0.0f, 0.0f};
    for (int kk = kh * 14; kk < kh * 14 + 14; kk++) {
        unsigned a[4], b[2];
        const float* pp = Ssh + qr * SLD + kk * 8 + qk;
        a[0] = __float_as_uint(pp[0]);
        a[1] = __float_as_uint(pp[8 * SLD]);
        a[2] = __float_as_uint(pp[4]);
        a[3] = __float_as_uint(pp[8 * SLD + 4]);
        b[0] = __float_as_uint(Ksh[(kk * 8 + qk) * KLD + nt2 * 8 + qr]);
        b[1] = __float_as_uint(Ksh[(kk * 8 + qk + 4) * KLD + nt2 * 8 + qr]);
        mma16n8k8(facc, a, b);
    }

    // reduce the two k-halves through Qsh (free), gate-multiply, store
    if (kh == 1) {
        *(float2*)(Qsh + qr * KLD + nt2 * 8 + 2 * qk)       = make_float2(facc[0], facc[1]);
        *(float2*)(Qsh + (qr + 8) * KLD + nt2 * 8 + 2 * qk) = make_float2(facc[2], facc[3]);
    }
    __syncthreads();
    if (kh == 0) {
        const int cc = nt2 * 8 + 2 * qk;
        const float2 p0 = *(const float2*)(Qsh + qr * KLD + cc);
        const float2 p1 = *(const float2*)(Qsh + (qr + 8) * KLD + cc);
        const float2 g0 = *(const float2*)(Gsh + qr * KLD + cc);
        const float2 g1 = *(const float2*)(Gsh + (qr + 8) * KLD + cc);
        float2 r0, r1;
        r0.x = (facc[0] + p0.x) * g0.x;
        r0.y = (facc[1] + p0.y) * g0.y;
        r1.x = (facc[2] + p1.x) * g1.x;
        r1.y = (facc[3] + p1.y) * g1.y;
        *(float2*)(attn_out + (size_t)(n0 + qr) * DMODEL + h * HDIM + cc)     = r0;
        *(float2*)(attn_out + (size_t)(n0 + qr + 8) * DMODEL + h * HDIM + cc) = r1;
    }
}

// ---------------------------------------------------------------------------
// Launch
// ---------------------------------------------------------------------------
extern "C" void kernel_launch(void* const* d_in, const int* in_sizes, int n_in,
                              void* d_out, int out_size)
{
    const float* x        = (const float*)d_in[0];
    const float* Wqkv     = (const float*)d_in[1];
    const float* bqkv     = (const float*)d_in[2];
    const float* Wgate    = (const float*)d_in[3];
    const float* bgate    = (const float*)d_in[4];
    const float* Wout     = (const float*)d_in[5];
    const float* bout     = (const float*)d_in[6];
    const float* pos_bias = (const float*)d_in[7];
    const int*   offsets  = (const int*)d_in[8];
    const int NO = in_sizes[8];

    float *qkv_p, *gate_p, *attn_p;
    cudaGetSymbolAddress((void**)&qkv_p,  g_qkv);
    cudaGetSymbolAddress((void**)&gate_p, g_gate);
    cudaGetSymbolAddress((void**)&attn_p, g_attn);

    cudaFuncSetAttribute(mma_gemm, cudaFuncAttributeMaxDynamicSharedMemorySize,
                         GEMM_SMEM_BYTES);
    cudaFuncSetAttribute(attn_kernel, cudaFuncAttributeMaxDynamicSharedMemorySize,
                         ATTN_SMEM_BYTES);

    // 1) fused: qkv = x@Wqkv^T+bqkv  AND  gate = sigmoid(x@Wgate^T+bgate)
    mma_gemm<<<dim3(QG_W / BN, NSEQ / BM), 128, GEMM_SMEM_BYTES>>>(
        x,
        Wqkv,  bqkv,  qkv_p,  QKV_W,
        Wgate, bgate, gate_p, DMODEL,
        DMODEL, QKV_W);

    // 2) attention + gate multiply
    attn_kernel<<<dim3(NSEQ / QT, NHEAD), 512, ATTN_SMEM_BYTES>>>(
        qkv_p, gate_p, pos_bias, offsets, attn_p, NO);

    // 3) out = (attn*gate) @ Wout^T + bout
    mma_gemm<<<dim3(DMODEL / BN, NSEQ / BM), 128, GEMM_SMEM_BYTES>>>(
        attn_p,
        Wout, bout, (float*)d_out, DMODEL,
        Wout, bout, (float*)d_out, DMODEL,
        DMODEL, 1 << 30);
}